// round 1
// baseline (speedup 1.0000x reference)
#include <cuda_runtime.h>
#include <math.h>

#define N_NODES 50000
#define IN_DIM  256
#define OUT_DIM 128
#define HEADS   2
#define F_OUT   256   /* OUT_DIM*HEADS */
#define N_EDGES 800000

/* ---------------- scratch (no allocation allowed) ---------------- */
__device__ float        g_Wh[(size_t)N_NODES * F_OUT];     /* 51.2 MB */
__device__ float        g_s[N_NODES * HEADS];
__device__ float        g_t[N_NODES * HEADS];
__device__ unsigned int g_m[N_NODES * HEADS];              /* order-key encoded max */
__device__ float        g_denom[N_NODES * HEADS];
__device__ int          g_deg[N_NODES];
__device__ float        g_e[(size_t)N_EDGES * HEADS];      /* e, then overwritten with ex */
__device__ int          g_is64;

/* ---------------- helpers ---------------- */
__device__ __forceinline__ unsigned int f2key(float v) {
    unsigned int u = __float_as_uint(v);
    return (u & 0x80000000u) ? ~u : (u | 0x80000000u);
}
__device__ __forceinline__ float key2f(unsigned int k) {
    unsigned int u = (k & 0x80000000u) ? (k ^ 0x80000000u) : ~k;
    return __uint_as_float(u);
}
__device__ __forceinline__ void load_edge(const int* ei, int i, int is64, int& src, int& dst) {
    if (is64) { src = ei[2 * i]; dst = ei[2 * (N_EDGES + i)]; }
    else      { src = ei[i];     dst = ei[N_EDGES + i]; }
}

/* ---------------- 0: detect int32 vs int64 edge_index ---------------- */
__global__ void detect_kernel(const int* ei) {
    if (threadIdx.x == 0 && blockIdx.x == 0) {
        int all_zero = 1;
        for (int i = 0; i < 256; i++) {
            if (ei[2 * i + 1] != 0) { all_zero = 0; break; }
        }
        g_is64 = all_zero;
    }
}

/* ---------------- 1: init ---------------- */
__global__ void init_kernel(float* out) {
    int idx = blockIdx.x * blockDim.x + threadIdx.x;
    int total = N_NODES * F_OUT;
    for (int i = idx; i < total; i += gridDim.x * blockDim.x) {
        out[i] = 0.0f;
        if (i < N_NODES * HEADS) { g_m[i] = 0u; g_denom[i] = 0.0f; }
        if (i < N_NODES)         { g_deg[i] = 0; }
    }
}

/* ---------------- 2: SGEMM Wh = x @ W + b  (128x128x16, 256 thr, 8x8/thr) -------- */
__global__ void __launch_bounds__(256) gemm_kernel(const float* __restrict__ A,
                                                   const float* __restrict__ W,
                                                   const float* __restrict__ bias) {
    __shared__ float As[16][128];
    __shared__ float Bs[16][128];
    const int bm = blockIdx.y * 128;
    const int bn = blockIdx.x * 128;
    const int tid = threadIdx.x;
    const int tx = tid & 15;     /* 16 column groups */
    const int ty = tid >> 4;     /* 16 row groups */
    float acc[8][8];
    #pragma unroll
    for (int i = 0; i < 8; i++)
        #pragma unroll
        for (int j = 0; j < 8; j++) acc[i][j] = 0.0f;

    for (int k0 = 0; k0 < IN_DIM; k0 += 16) {
        #pragma unroll
        for (int i = 0; i < 8; i++) {
            int idx = tid + i * 256;           /* 0..2047 */
            int r = idx >> 4, c = idx & 15;
            int gr = bm + r;
            As[c][r] = (gr < N_NODES) ? A[(size_t)gr * IN_DIM + k0 + c] : 0.0f;
        }
        #pragma unroll
        for (int i = 0; i < 8; i++) {
            int idx = tid + i * 256;
            int r = idx >> 7, c = idx & 127;
            Bs[r][c] = W[(size_t)(k0 + r) * F_OUT + bn + c];
        }
        __syncthreads();
        #pragma unroll
        for (int kk = 0; kk < 16; kk++) {
            float a[8], b[8];
            #pragma unroll
            for (int i = 0; i < 8; i++) a[i] = As[kk][ty * 8 + i];
            #pragma unroll
            for (int j = 0; j < 8; j++) b[j] = Bs[kk][tx * 8 + j];
            #pragma unroll
            for (int i = 0; i < 8; i++)
                #pragma unroll
                for (int j = 0; j < 8; j++)
                    acc[i][j] = fmaf(a[i], b[j], acc[i][j]);
        }
        __syncthreads();
    }
    #pragma unroll
    for (int i = 0; i < 8; i++) {
        int gr = bm + ty * 8 + i;
        if (gr < N_NODES) {
            #pragma unroll
            for (int j = 0; j < 8; j++) {
                int gc = bn + tx * 8 + j;
                g_Wh[(size_t)gr * F_OUT + gc] = acc[i][j] + bias[gc];
            }
        }
    }
}

/* ---------------- 3: per-(node,head) attention dots s,t (warp each) -------- */
__global__ void st_kernel(const float* __restrict__ a_vec) {
    int w = (blockIdx.x * blockDim.x + threadIdx.x) >> 5;
    int lane = threadIdx.x & 31;
    if (w >= N_NODES * HEADS) return;
    int n = w / HEADS, h = w - n * HEADS;
    const float* row = g_Wh + (size_t)n * F_OUT + h * OUT_DIM;
    float s = 0.0f, t = 0.0f;
    #pragma unroll
    for (int i = 0; i < 4; i++) {
        float v = row[lane + 32 * i];
        s = fmaf(v, a_vec[lane + 32 * i], s);
        t = fmaf(v, a_vec[OUT_DIM + lane + 32 * i], t);
    }
    #pragma unroll
    for (int o = 16; o > 0; o >>= 1) {
        s += __shfl_down_sync(0xffffffffu, s, o);
        t += __shfl_down_sync(0xffffffffu, t, o);
    }
    if (lane == 0) { g_s[w] = s; g_t[w] = t; }
}

/* ---------------- 4: per-edge e + segment max + degree ---------------- */
__global__ void edge_max_kernel(const int* __restrict__ ei) {
    int i = blockIdx.x * blockDim.x + threadIdx.x;
    if (i >= N_EDGES) return;
    int is64 = g_is64;
    int src, dst;
    load_edge(ei, i, is64, src, dst);
    atomicAdd(&g_deg[src], 1);
    #pragma unroll
    for (int h = 0; h < HEADS; h++) {
        float v = g_s[src * HEADS + h] + g_t[dst * HEADS + h];
        v = v > 0.0f ? v : 0.2f * v;
        g_e[(size_t)h * N_EDGES + i] = v;
        atomicMax(&g_m[src * HEADS + h], f2key(v));
    }
}

/* ---------------- 5: per-edge exp + segment sum ---------------- */
__global__ void edge_exp_kernel(const int* __restrict__ ei) {
    int i = blockIdx.x * blockDim.x + threadIdx.x;
    if (i >= N_EDGES) return;
    int is64 = g_is64;
    int src, dst;
    load_edge(ei, i, is64, src, dst);
    #pragma unroll
    for (int h = 0; h < HEADS; h++) {
        float m = key2f(g_m[src * HEADS + h]);
        float ex = expf(g_e[(size_t)h * N_EDGES + i] - m);
        g_e[(size_t)h * N_EDGES + i] = ex;
        atomicAdd(&g_denom[src * HEADS + h], ex);
    }
}

/* ---------------- 6: aggregation (warp per edge, atomic scatter) ------- */
__global__ void edge_agg_kernel(const int* __restrict__ ei, float* __restrict__ out) {
    int w = (blockIdx.x * blockDim.x + threadIdx.x) >> 5;
    int lane = threadIdx.x & 31;
    if (w >= N_EDGES) return;
    int is64 = g_is64;
    int src, dst;
    load_edge(ei, w, is64, src, dst);
    float alpha0 = g_e[w]           / g_denom[src * HEADS + 0];
    float alpha1 = g_e[N_EDGES + w] / g_denom[src * HEADS + 1];
    const float4* whd = (const float4*)(g_Wh + (size_t)dst * F_OUT);
    float* o = out + (size_t)src * F_OUT;
    #pragma unroll
    for (int i = 0; i < 2; i++) {
        int f4 = lane + 32 * i;                 /* 0..63 float4s */
        float alpha = (f4 < 32) ? alpha0 : alpha1;
        float4 v = whd[f4];
        int base = f4 * 4;
        atomicAdd(&o[base + 0], alpha * v.x);
        atomicAdd(&o[base + 1], alpha * v.y);
        atomicAdd(&o[base + 2], alpha * v.z);
        atomicAdd(&o[base + 3], alpha * v.w);
    }
}

/* ---------------- 7: deg==0 fallback: h' = Wh ---------------- */
__global__ void finalize_kernel(float* __restrict__ out) {
    int idx = blockIdx.x * blockDim.x + threadIdx.x;
    if (idx >= N_NODES * F_OUT) return;
    int n = idx >> 8; /* /F_OUT */
    if (g_deg[n] == 0) out[idx] = g_Wh[idx];
}

/* ---------------- launch ---------------- */
extern "C" void kernel_launch(void* const* d_in, const int* in_sizes, int n_in,
                              void* d_out, int out_size) {
    const float* x  = (const float*)d_in[0];
    const int*   ei = (const int*)d_in[1];
    const float* Ww = (const float*)d_in[2];
    const float* Wb = (const float*)d_in[3];
    const float* a  = (const float*)d_in[4];
    float* out = (float*)d_out;

    detect_kernel<<<1, 32>>>(ei);

    init_kernel<<<1024, 256>>>(out);

    dim3 ggrid(F_OUT / 128, (N_NODES + 127) / 128);
    gemm_kernel<<<ggrid, 256>>>(x, Ww, Wb);

    {
        int warps = N_NODES * HEADS;
        int threads = warps * 32;
        st_kernel<<<(threads + 255) / 256, 256>>>(a);
    }

    edge_max_kernel<<<(N_EDGES + 255) / 256, 256>>>(ei);
    edge_exp_kernel<<<(N_EDGES + 255) / 256, 256>>>(ei);

    {
        long long threads = (long long)N_EDGES * 32;
        edge_agg_kernel<<<(int)((threads + 255) / 256), 256>>>(ei, out);
    }

    finalize_kernel<<<(N_NODES * F_OUT + 255) / 256, 256>>>(out);
}

// round 2
// speedup vs baseline: 2.5231x; 2.5231x over previous
#include <cuda_runtime.h>
#include <math.h>

#define N_NODES 50000
#define IN_DIM  256
#define OUT_DIM 128
#define HEADS   2
#define F_OUT   256
#define N_EDGES 800000

/* ---------------- scratch ---------------- */
__device__ float g_Wh[(size_t)N_NODES * F_OUT];   /* 51.2 MB */
__device__ float g_s[N_NODES * HEADS];
__device__ float g_t[N_NODES * HEADS];
__device__ int   g_deg[N_NODES];
__device__ int   g_row[N_NODES + 1];
__device__ int   g_cursor[N_NODES];
__device__ int   g_csr_dst[N_EDGES];
__device__ int   g_is64;

__device__ __forceinline__ void load_edge(const int* ei, int i, int is64, int& src, int& dst) {
    if (is64) { src = ei[2 * i]; dst = ei[2 * (N_EDGES + i)]; }
    else      { src = ei[i];     dst = ei[N_EDGES + i]; }
}

/* ---------------- 0: detect int32 vs int64 ---------------- */
__global__ void detect_kernel(const int* ei) {
    if (threadIdx.x == 0 && blockIdx.x == 0) {
        int all_zero = 1;
        for (int i = 0; i < 256; i++)
            if (ei[2 * i + 1] != 0) { all_zero = 0; break; }
        g_is64 = all_zero;
    }
}

/* ---------------- 1: init deg ---------------- */
__global__ void init_kernel() {
    int i = blockIdx.x * blockDim.x + threadIdx.x;
    if (i < N_NODES) g_deg[i] = 0;
}

/* ---------------- 2: 3xTF32 MMA GEMM  Wh = x@W + b ----------------
   block tile 128x64, 8 warps (4M x 2N), warp tile 32x32, k-chunk 32 */
__device__ __forceinline__ unsigned int f2tf(float f) {
    unsigned int u;
    asm("cvt.rna.tf32.f32 %0, %1;" : "=r"(u) : "f"(f));
    return u;
}
__device__ __forceinline__ void mma_tf32(float c[4], unsigned int a0, unsigned int a1,
                                         unsigned int a2, unsigned int a3,
                                         unsigned int b0, unsigned int b1) {
    asm volatile(
        "mma.sync.aligned.m16n8k8.row.col.f32.tf32.tf32.f32 "
        "{%0,%1,%2,%3},{%4,%5,%6,%7},{%8,%9},{%0,%1,%2,%3};"
        : "+f"(c[0]), "+f"(c[1]), "+f"(c[2]), "+f"(c[3])
        : "r"(a0), "r"(a1), "r"(a2), "r"(a3), "r"(b0), "r"(b1));
}

__global__ void __launch_bounds__(256) gemm_kernel(const float* __restrict__ A,
                                                   const float* __restrict__ W,
                                                   const float* __restrict__ bias) {
    __shared__ float As[32][132];   /* [k][row] */
    __shared__ float Bs[32][68];    /* [k][n]   */
    const int bm = blockIdx.y * 128;
    const int bn = blockIdx.x * 64;
    const int tid  = threadIdx.x;
    const int lane = tid & 31;
    const int wid  = tid >> 5;
    const int warp_m = wid >> 1;         /* 0..3 */
    const int warp_n = wid & 1;          /* 0..1 */
    const int g  = lane >> 2;            /* 0..7 */
    const int tc = lane & 3;             /* 0..3 */

    float c[2][4][4];
    #pragma unroll
    for (int mi = 0; mi < 2; mi++)
        #pragma unroll
        for (int ni = 0; ni < 4; ni++)
            #pragma unroll
            for (int r = 0; r < 4; r++) c[mi][ni][r] = 0.0f;

    for (int k0 = 0; k0 < IN_DIM; k0 += 32) {
        /* load A tile 128x32 */
        #pragma unroll
        for (int p = 0; p < 4; p++) {
            int row = p * 32 + (tid >> 3);
            int kq  = (tid & 7) * 4;
            int gr  = bm + row;
            float4 v = make_float4(0.f, 0.f, 0.f, 0.f);
            if (gr < N_NODES)
                v = *(const float4*)&A[(size_t)gr * IN_DIM + k0 + kq];
            As[kq + 0][row] = v.x;
            As[kq + 1][row] = v.y;
            As[kq + 2][row] = v.z;
            As[kq + 3][row] = v.w;
        }
        /* load B tile 32x64 */
        #pragma unroll
        for (int p = 0; p < 2; p++) {
            int id = tid + p * 256;       /* float4 id 0..511 */
            int k  = id >> 4;
            int n4 = id & 15;
            float4 v = *(const float4*)&W[(size_t)(k0 + k) * F_OUT + bn + n4 * 4];
            *(float4*)&Bs[k][n4 * 4] = v;
        }
        __syncthreads();

        #pragma unroll
        for (int kk = 0; kk < 4; kk++) {
            unsigned int ah[2][4], al[2][4], bh[4][2], bl[4][2];
            #pragma unroll
            for (int mi = 0; mi < 2; mi++) {
                int rb = warp_m * 32 + mi * 16;
                float a0 = As[kk * 8 + tc][rb + g];
                float a1 = As[kk * 8 + tc][rb + g + 8];
                float a2 = As[kk * 8 + tc + 4][rb + g];
                float a3 = As[kk * 8 + tc + 4][rb + g + 8];
                ah[mi][0] = f2tf(a0); al[mi][0] = f2tf(a0 - __uint_as_float(ah[mi][0]));
                ah[mi][1] = f2tf(a1); al[mi][1] = f2tf(a1 - __uint_as_float(ah[mi][1]));
                ah[mi][2] = f2tf(a2); al[mi][2] = f2tf(a2 - __uint_as_float(ah[mi][2]));
                ah[mi][3] = f2tf(a3); al[mi][3] = f2tf(a3 - __uint_as_float(ah[mi][3]));
            }
            #pragma unroll
            for (int ni = 0; ni < 4; ni++) {
                int n = warp_n * 32 + ni * 8 + g;
                float b0 = Bs[kk * 8 + tc][n];
                float b1 = Bs[kk * 8 + tc + 4][n];
                bh[ni][0] = f2tf(b0); bl[ni][0] = f2tf(b0 - __uint_as_float(bh[ni][0]));
                bh[ni][1] = f2tf(b1); bl[ni][1] = f2tf(b1 - __uint_as_float(bh[ni][1]));
            }
            #pragma unroll
            for (int mi = 0; mi < 2; mi++)
                #pragma unroll
                for (int ni = 0; ni < 4; ni++) {
                    mma_tf32(c[mi][ni], al[mi][0], al[mi][1], al[mi][2], al[mi][3],
                             bh[ni][0], bh[ni][1]);
                    mma_tf32(c[mi][ni], ah[mi][0], ah[mi][1], ah[mi][2], ah[mi][3],
                             bl[ni][0], bl[ni][1]);
                    mma_tf32(c[mi][ni], ah[mi][0], ah[mi][1], ah[mi][2], ah[mi][3],
                             bh[ni][0], bh[ni][1]);
                }
        }
        __syncthreads();
    }

    /* epilogue */
    #pragma unroll
    for (int mi = 0; mi < 2; mi++) {
        int r0 = bm + warp_m * 32 + mi * 16 + g;
        int r1 = r0 + 8;
        #pragma unroll
        for (int ni = 0; ni < 4; ni++) {
            int cb = bn + warp_n * 32 + ni * 8 + tc * 2;
            float b0 = bias[cb], b1 = bias[cb + 1];
            if (r0 < N_NODES) {
                g_Wh[(size_t)r0 * F_OUT + cb]     = c[mi][ni][0] + b0;
                g_Wh[(size_t)r0 * F_OUT + cb + 1] = c[mi][ni][1] + b1;
            }
            if (r1 < N_NODES) {
                g_Wh[(size_t)r1 * F_OUT + cb]     = c[mi][ni][2] + b0;
                g_Wh[(size_t)r1 * F_OUT + cb + 1] = c[mi][ni][3] + b1;
            }
        }
    }
}

/* ---------------- 3: attention dots s,t (warp per node-head) -------- */
__global__ void st_kernel(const float* __restrict__ a_vec) {
    int w = (blockIdx.x * blockDim.x + threadIdx.x) >> 5;
    int lane = threadIdx.x & 31;
    if (w >= N_NODES * HEADS) return;
    int n = w / HEADS, h = w - n * HEADS;
    const float* row = g_Wh + (size_t)n * F_OUT + h * OUT_DIM;
    float s = 0.0f, t = 0.0f;
    #pragma unroll
    for (int i = 0; i < 4; i++) {
        float v = row[lane + 32 * i];
        s = fmaf(v, a_vec[lane + 32 * i], s);
        t = fmaf(v, a_vec[OUT_DIM + lane + 32 * i], t);
    }
    #pragma unroll
    for (int o = 16; o > 0; o >>= 1) {
        s += __shfl_down_sync(0xffffffffu, s, o);
        t += __shfl_down_sync(0xffffffffu, t, o);
    }
    if (lane == 0) { g_s[w] = s; g_t[w] = t; }
}

/* ---------------- 4: degree histogram ---------------- */
__global__ void deg_kernel(const int* __restrict__ ei) {
    int i = blockIdx.x * blockDim.x + threadIdx.x;
    if (i >= N_EDGES) return;
    int src = g_is64 ? ei[2 * i] : ei[i];
    atomicAdd(&g_deg[src], 1);
}

/* ---------------- 5: single-block exclusive scan ---------------- */
__global__ void scan_kernel() {
    const int tid = threadIdx.x, lane = tid & 31, wid = tid >> 5;
    __shared__ int wsum[32];
    __shared__ int s_carry;
    if (tid == 0) s_carry = 0;
    __syncthreads();
    for (int base = 0; base < N_NODES; base += 1024) {
        int i = base + tid;
        int v = (i < N_NODES) ? g_deg[i] : 0;
        int x = v;
        #pragma unroll
        for (int o = 1; o < 32; o <<= 1) {
            int y = __shfl_up_sync(0xffffffffu, x, o);
            if (lane >= o) x += y;
        }
        if (lane == 31) wsum[wid] = x;
        __syncthreads();
        if (wid == 0) {
            int w = wsum[lane];
            #pragma unroll
            for (int o = 1; o < 32; o <<= 1) {
                int y = __shfl_up_sync(0xffffffffu, w, o);
                if (lane >= o) w += y;
            }
            wsum[lane] = w;
        }
        __syncthreads();
        int warp_off = (wid == 0) ? 0 : wsum[wid - 1];
        int excl = s_carry + warp_off + x - v;
        if (i < N_NODES) { g_row[i] = excl; g_cursor[i] = excl; }
        __syncthreads();
        if (tid == 0) s_carry += wsum[31];
        __syncthreads();
    }
    if (tid == 0) g_row[N_NODES] = s_carry;
}

/* ---------------- 6: scatter into CSR ---------------- */
__global__ void scatter_kernel(const int* __restrict__ ei) {
    int i = blockIdx.x * blockDim.x + threadIdx.x;
    if (i >= N_EDGES) return;
    int src, dst;
    load_edge(ei, i, g_is64, src, dst);
    int p = atomicAdd(&g_cursor[src], 1);
    g_csr_dst[p] = dst;
}

/* ---------------- 7: fused agg (warp per node) ---------------- */
__global__ void __launch_bounds__(256) agg_kernel(float* __restrict__ out) {
    int n = (blockIdx.x * blockDim.x + threadIdx.x) >> 5;
    int lane = threadIdx.x & 31;
    if (n >= N_NODES) return;
    int start = g_row[n], end = g_row[n + 1];
    float* o = out + (size_t)n * F_OUT + lane * 8;
    const float* whn = g_Wh + (size_t)n * F_OUT + lane * 8;

    if (start == end) {
        /* deg==0: out = Wh */
        float4 v0 = *(const float4*)whn;
        float4 v1 = *(const float4*)(whn + 4);
        *(float4*)o = v0;
        *(float4*)(o + 4) = v1;
        return;
    }

    float s0 = g_s[2 * n], s1 = g_s[2 * n + 1];

    /* pass1: segment max (both heads), edges strided across lanes */
    float m0 = -INFINITY, m1 = -INFINITY;
    for (int i = start + lane; i < end; i += 32) {
        int d = g_csr_dst[i];
        float2 t = *(const float2*)&g_t[2 * d];
        float e0 = s0 + t.x; e0 = e0 > 0.f ? e0 : 0.2f * e0;
        float e1 = s1 + t.y; e1 = e1 > 0.f ? e1 : 0.2f * e1;
        m0 = fmaxf(m0, e0);
        m1 = fmaxf(m1, e1);
    }
    #pragma unroll
    for (int off = 16; off > 0; off >>= 1) {
        m0 = fmaxf(m0, __shfl_xor_sync(0xffffffffu, m0, off));
        m1 = fmaxf(m1, __shfl_xor_sync(0xffffffffu, m1, off));
    }

    /* pass2: sequential edges, all lanes cooperate on channels */
    int head = lane >> 4;
    float s_h = head ? s1 : s0;
    float m_h = head ? m1 : m0;
    float4 acc0 = make_float4(0.f, 0.f, 0.f, 0.f);
    float4 acc1 = make_float4(0.f, 0.f, 0.f, 0.f);
    float den = 0.0f;
    int d = g_csr_dst[start];
    for (int i = start; i < end; i++) {
        int dn = (i + 1 < end) ? g_csr_dst[i + 1] : 0;
        float t = g_t[2 * d + head];
        float e = s_h + t; e = e > 0.f ? e : 0.2f * e;
        float ex = expf(e - m_h);
        den += ex;
        const float4* w = (const float4*)(g_Wh + (size_t)d * F_OUT + lane * 8);
        float4 v0 = w[0], v1 = w[1];
        acc0.x = fmaf(ex, v0.x, acc0.x); acc0.y = fmaf(ex, v0.y, acc0.y);
        acc0.z = fmaf(ex, v0.z, acc0.z); acc0.w = fmaf(ex, v0.w, acc0.w);
        acc1.x = fmaf(ex, v1.x, acc1.x); acc1.y = fmaf(ex, v1.y, acc1.y);
        acc1.z = fmaf(ex, v1.z, acc1.z); acc1.w = fmaf(ex, v1.w, acc1.w);
        d = dn;
    }
    float inv = 1.0f / den;
    acc0.x *= inv; acc0.y *= inv; acc0.z *= inv; acc0.w *= inv;
    acc1.x *= inv; acc1.y *= inv; acc1.z *= inv; acc1.w *= inv;
    *(float4*)o = acc0;
    *(float4*)(o + 4) = acc1;
}

/* ---------------- launch ---------------- */
extern "C" void kernel_launch(void* const* d_in, const int* in_sizes, int n_in,
                              void* d_out, int out_size) {
    const float* x  = (const float*)d_in[0];
    const int*   ei = (const int*)d_in[1];
    const float* Ww = (const float*)d_in[2];
    const float* Wb = (const float*)d_in[3];
    const float* a  = (const float*)d_in[4];
    float* out = (float*)d_out;

    detect_kernel<<<1, 32>>>(ei);
    init_kernel<<<(N_NODES + 255) / 256, 256>>>();

    dim3 ggrid(F_OUT / 64, (N_NODES + 127) / 128);
    gemm_kernel<<<ggrid, 256>>>(x, Ww, Wb);

    st_kernel<<<(N_NODES * HEADS * 32 + 255) / 256, 256>>>(a);

    deg_kernel<<<(N_EDGES + 255) / 256, 256>>>(ei);
    scan_kernel<<<1, 1024>>>();
    scatter_kernel<<<(N_EDGES + 255) / 256, 256>>>(ei);

    agg_kernel<<<(N_NODES * 32 + 255) / 256, 256>>>(out);
}

// round 3
// speedup vs baseline: 2.5669x; 1.0174x over previous
#include <cuda_runtime.h>
#include <math.h>

#define N_NODES 50000
#define IN_DIM  256
#define OUT_DIM 128
#define HEADS   2
#define F_OUT   256
#define N_EDGES 800000

/* ---------------- scratch ---------------- */
__device__ float g_Wh[(size_t)N_NODES * F_OUT];   /* 51.2 MB */
__device__ float g_s[N_NODES * HEADS];
__device__ float g_t[N_NODES * HEADS];
__device__ int   g_deg[N_NODES];
__device__ int   g_row[N_NODES + 1];
__device__ int   g_cursor[N_NODES];
__device__ int   g_csr_dst[N_EDGES];
__device__ int   g_esrc[N_EDGES];
__device__ int   g_edst[N_EDGES];
__device__ int   g_is64;

/* ---------------- 0: detect int32 vs int64 (parallel) ---------------- */
__global__ void detect_kernel(const int* ei) {
    int v = ei[2 * threadIdx.x + 1];
    int any = __syncthreads_or(v != 0);
    if (threadIdx.x == 0) g_is64 = !any;
}

/* ---------------- 1: init deg + s/t accumulators ---------------- */
__global__ void init_kernel() {
    int i = blockIdx.x * blockDim.x + threadIdx.x;
    if (i < N_NODES) g_deg[i] = 0;
    if (i < N_NODES * HEADS) { g_s[i] = 0.0f; g_t[i] = 0.0f; }
}

/* ---------------- 2: 3xTF32 MMA GEMM  Wh = x@W + b, fused s/t epilogue --- */
__device__ __forceinline__ unsigned int f2tf(float f) {
    unsigned int u;
    asm("cvt.rna.tf32.f32 %0, %1;" : "=r"(u) : "f"(f));
    return u;
}
__device__ __forceinline__ void mma_tf32(float c[4], unsigned int a0, unsigned int a1,
                                         unsigned int a2, unsigned int a3,
                                         unsigned int b0, unsigned int b1) {
    asm volatile(
        "mma.sync.aligned.m16n8k8.row.col.f32.tf32.tf32.f32 "
        "{%0,%1,%2,%3},{%4,%5,%6,%7},{%8,%9},{%0,%1,%2,%3};"
        : "+f"(c[0]), "+f"(c[1]), "+f"(c[2]), "+f"(c[3])
        : "r"(a0), "r"(a1), "r"(a2), "r"(a3), "r"(b0), "r"(b1));
}

__global__ void __launch_bounds__(256) gemm_kernel(const float* __restrict__ A,
                                                   const float* __restrict__ W,
                                                   const float* __restrict__ bias,
                                                   const float* __restrict__ a_vec) {
    __shared__ float As[32][132];   /* [k][row] */
    __shared__ float Bs[32][68];    /* [k][n]   */
    const int bm = blockIdx.y * 128;
    const int bn = blockIdx.x * 64;
    const int tid  = threadIdx.x;
    const int lane = tid & 31;
    const int wid  = tid >> 5;
    const int warp_m = wid >> 1;
    const int warp_n = wid & 1;
    const int g  = lane >> 2;
    const int tc = lane & 3;
    const int head = (bn >= 128) ? 1 : 0;

    float c[2][4][4];
    #pragma unroll
    for (int mi = 0; mi < 2; mi++)
        #pragma unroll
        for (int ni = 0; ni < 4; ni++)
            #pragma unroll
            for (int r = 0; r < 4; r++) c[mi][ni][r] = 0.0f;

    for (int k0 = 0; k0 < IN_DIM; k0 += 32) {
        #pragma unroll
        for (int p = 0; p < 4; p++) {
            int row = p * 32 + (tid >> 3);
            int kq  = (tid & 7) * 4;
            int gr  = bm + row;
            float4 v = make_float4(0.f, 0.f, 0.f, 0.f);
            if (gr < N_NODES)
                v = *(const float4*)&A[(size_t)gr * IN_DIM + k0 + kq];
            As[kq + 0][row] = v.x;
            As[kq + 1][row] = v.y;
            As[kq + 2][row] = v.z;
            As[kq + 3][row] = v.w;
        }
        #pragma unroll
        for (int p = 0; p < 2; p++) {
            int id = tid + p * 256;
            int k  = id >> 4;
            int n4 = id & 15;
            float4 v = *(const float4*)&W[(size_t)(k0 + k) * F_OUT + bn + n4 * 4];
            *(float4*)&Bs[k][n4 * 4] = v;
        }
        __syncthreads();

        #pragma unroll
        for (int kk = 0; kk < 4; kk++) {
            unsigned int ah[2][4], al[2][4], bh[4][2], bl[4][2];
            #pragma unroll
            for (int mi = 0; mi < 2; mi++) {
                int rb = warp_m * 32 + mi * 16;
                float a0 = As[kk * 8 + tc][rb + g];
                float a1 = As[kk * 8 + tc][rb + g + 8];
                float a2 = As[kk * 8 + tc + 4][rb + g];
                float a3 = As[kk * 8 + tc + 4][rb + g + 8];
                ah[mi][0] = f2tf(a0); al[mi][0] = f2tf(a0 - __uint_as_float(ah[mi][0]));
                ah[mi][1] = f2tf(a1); al[mi][1] = f2tf(a1 - __uint_as_float(ah[mi][1]));
                ah[mi][2] = f2tf(a2); al[mi][2] = f2tf(a2 - __uint_as_float(ah[mi][2]));
                ah[mi][3] = f2tf(a3); al[mi][3] = f2tf(a3 - __uint_as_float(ah[mi][3]));
            }
            #pragma unroll
            for (int ni = 0; ni < 4; ni++) {
                int n = warp_n * 32 + ni * 8 + g;
                float b0 = Bs[kk * 8 + tc][n];
                float b1 = Bs[kk * 8 + tc + 4][n];
                bh[ni][0] = f2tf(b0); bl[ni][0] = f2tf(b0 - __uint_as_float(bh[ni][0]));
                bh[ni][1] = f2tf(b1); bl[ni][1] = f2tf(b1 - __uint_as_float(bh[ni][1]));
            }
            #pragma unroll
            for (int mi = 0; mi < 2; mi++)
                #pragma unroll
                for (int ni = 0; ni < 4; ni++) {
                    mma_tf32(c[mi][ni], al[mi][0], al[mi][1], al[mi][2], al[mi][3],
                             bh[ni][0], bh[ni][1]);
                    mma_tf32(c[mi][ni], ah[mi][0], ah[mi][1], ah[mi][2], ah[mi][3],
                             bl[ni][0], bl[ni][1]);
                    mma_tf32(c[mi][ni], ah[mi][0], ah[mi][1], ah[mi][2], ah[mi][3],
                             bh[ni][0], bh[ni][1]);
                }
        }
        __syncthreads();
    }

    /* epilogue: store Wh and accumulate partial s,t dots for this 64-col slab */
    #pragma unroll
    for (int mi = 0; mi < 2; mi++) {
        int r0 = bm + warp_m * 32 + mi * 16 + g;
        int r1 = r0 + 8;
        float ps0 = 0.f, pt0 = 0.f, ps1 = 0.f, pt1 = 0.f;
        #pragma unroll
        for (int ni = 0; ni < 4; ni++) {
            int cb = bn + warp_n * 32 + ni * 8 + tc * 2;
            int dloc = cb - head * OUT_DIM;
            float b0 = bias[cb], b1 = bias[cb + 1];
            float as0 = a_vec[dloc],          as1 = a_vec[dloc + 1];
            float ad0 = a_vec[OUT_DIM + dloc], ad1 = a_vec[OUT_DIM + dloc + 1];
            float v00 = c[mi][ni][0] + b0, v01 = c[mi][ni][1] + b1;
            float v10 = c[mi][ni][2] + b0, v11 = c[mi][ni][3] + b1;
            if (r0 < N_NODES) {
                g_Wh[(size_t)r0 * F_OUT + cb]     = v00;
                g_Wh[(size_t)r0 * F_OUT + cb + 1] = v01;
            }
            if (r1 < N_NODES) {
                g_Wh[(size_t)r1 * F_OUT + cb]     = v10;
                g_Wh[(size_t)r1 * F_OUT + cb + 1] = v11;
            }
            ps0 = fmaf(v00, as0, fmaf(v01, as1, ps0));
            pt0 = fmaf(v00, ad0, fmaf(v01, ad1, pt0));
            ps1 = fmaf(v10, as0, fmaf(v11, as1, ps1));
            pt1 = fmaf(v10, ad0, fmaf(v11, ad1, pt1));
        }
        /* reduce across the 4 tc lanes sharing a row */
        #pragma unroll
        for (int o = 2; o > 0; o >>= 1) {
            ps0 += __shfl_down_sync(0xffffffffu, ps0, o);
            pt0 += __shfl_down_sync(0xffffffffu, pt0, o);
            ps1 += __shfl_down_sync(0xffffffffu, ps1, o);
            pt1 += __shfl_down_sync(0xffffffffu, pt1, o);
        }
        if (tc == 0) {
            if (r0 < N_NODES) {
                atomicAdd(&g_s[2 * r0 + head], ps0);
                atomicAdd(&g_t[2 * r0 + head], pt0);
            }
            if (r1 < N_NODES) {
                atomicAdd(&g_s[2 * r1 + head], ps1);
                atomicAdd(&g_t[2 * r1 + head], pt1);
            }
        }
    }
}

/* ---------------- 3: degree histogram + edge decode ---------------- */
__global__ void deg_kernel(const int* __restrict__ ei) {
    int i = blockIdx.x * blockDim.x + threadIdx.x;
    if (i >= N_EDGES) return;
    int src, dst;
    if (g_is64) { src = ei[2 * i]; dst = ei[2 * (N_EDGES + i)]; }
    else        { src = ei[i];     dst = ei[N_EDGES + i]; }
    g_esrc[i] = src;
    g_edst[i] = dst;
    atomicAdd(&g_deg[src], 1);
}

/* ---------------- 4: single-block exclusive scan (8 items/thread) ---- */
__global__ void scan_kernel() {
    const int tid = threadIdx.x, lane = tid & 31, wid = tid >> 5;
    __shared__ int wsum[32];
    __shared__ int s_carry;
    if (tid == 0) s_carry = 0;
    __syncthreads();
    for (int base = 0; base < N_NODES; base += 8192) {
        int i0 = base + tid * 8;
        int v[8], pref[8];
        int run = 0;
        #pragma unroll
        for (int j = 0; j < 8; j++) {
            v[j] = (i0 + j < N_NODES) ? g_deg[i0 + j] : 0;
            pref[j] = run;
            run += v[j];
        }
        int x = run;
        #pragma unroll
        for (int o = 1; o < 32; o <<= 1) {
            int y = __shfl_up_sync(0xffffffffu, x, o);
            if (lane >= o) x += y;
        }
        if (lane == 31) wsum[wid] = x;
        __syncthreads();
        if (wid == 0) {
            int w = wsum[lane];
            #pragma unroll
            for (int o = 1; o < 32; o <<= 1) {
                int y = __shfl_up_sync(0xffffffffu, w, o);
                if (lane >= o) w += y;
            }
            wsum[lane] = w;
        }
        __syncthreads();
        int off = s_carry + ((wid == 0) ? 0 : wsum[wid - 1]) + (x - run);
        #pragma unroll
        for (int j = 0; j < 8; j++) {
            int i = i0 + j;
            if (i < N_NODES) { g_row[i] = off + pref[j]; g_cursor[i] = off + pref[j]; }
        }
        __syncthreads();
        if (tid == 0) s_carry += wsum[31];
        __syncthreads();
    }
    if (tid == 0) g_row[N_NODES] = s_carry;
}

/* ---------------- 5: scatter into CSR ---------------- */
__global__ void scatter_kernel() {
    int i = blockIdx.x * blockDim.x + threadIdx.x;
    if (i >= N_EDGES) return;
    int src = g_esrc[i];
    int p = atomicAdd(&g_cursor[src], 1);
    g_csr_dst[p] = g_edst[i];
}

/* ---------------- 6: fused softmax+agg (warp per node, no max pass) --- */
__global__ void __launch_bounds__(256) agg_kernel(float* __restrict__ out) {
    int n = (blockIdx.x * blockDim.x + threadIdx.x) >> 5;
    int lane = threadIdx.x & 31;
    if (n >= N_NODES) return;
    int start = g_row[n], end = g_row[n + 1];
    float* o = out + (size_t)n * F_OUT + lane * 8;
    const float* whn = g_Wh + (size_t)n * F_OUT + lane * 8;

    if (start == end) {
        *(float4*)o       = *(const float4*)whn;
        *(float4*)(o + 4) = *(const float4*)(whn + 4);
        return;
    }

    int head = lane >> 4;
    float s_h = g_s[2 * n + head];
    float4 acc0 = make_float4(0.f, 0.f, 0.f, 0.f);
    float4 acc1 = make_float4(0.f, 0.f, 0.f, 0.f);
    float den = 0.0f;

    int i = start;
    for (; i + 1 < end; i += 2) {
        int d0 = g_csr_dst[i];
        int d1 = g_csr_dst[i + 1];
        float t0 = g_t[2 * d0 + head];
        float t1 = g_t[2 * d1 + head];
        const float4* w0 = (const float4*)(g_Wh + (size_t)d0 * F_OUT + lane * 8);
        const float4* w1 = (const float4*)(g_Wh + (size_t)d1 * F_OUT + lane * 8);
        float4 v00 = w0[0], v01 = w0[1];
        float4 v10 = w1[0], v11 = w1[1];
        float e0 = s_h + t0; e0 = e0 > 0.f ? e0 : 0.2f * e0;
        float e1 = s_h + t1; e1 = e1 > 0.f ? e1 : 0.2f * e1;
        float ex0 = expf(e0);
        float ex1 = expf(e1);
        den += ex0 + ex1;
        acc0.x = fmaf(ex0, v00.x, acc0.x); acc0.y = fmaf(ex0, v00.y, acc0.y);
        acc0.z = fmaf(ex0, v00.z, acc0.z); acc0.w = fmaf(ex0, v00.w, acc0.w);
        acc1.x = fmaf(ex0, v01.x, acc1.x); acc1.y = fmaf(ex0, v01.y, acc1.y);
        acc1.z = fmaf(ex0, v01.z, acc1.z); acc1.w = fmaf(ex0, v01.w, acc1.w);
        acc0.x = fmaf(ex1, v10.x, acc0.x); acc0.y = fmaf(ex1, v10.y, acc0.y);
        acc0.z = fmaf(ex1, v10.z, acc0.z); acc0.w = fmaf(ex1, v10.w, acc0.w);
        acc1.x = fmaf(ex1, v11.x, acc1.x); acc1.y = fmaf(ex1, v11.y, acc1.y);
        acc1.z = fmaf(ex1, v11.z, acc1.z); acc1.w = fmaf(ex1, v11.w, acc1.w);
    }
    if (i < end) {
        int d = g_csr_dst[i];
        float t = g_t[2 * d + head];
        const float4* w = (const float4*)(g_Wh + (size_t)d * F_OUT + lane * 8);
        float4 v0 = w[0], v1 = w[1];
        float e = s_h + t; e = e > 0.f ? e : 0.2f * e;
        float ex = expf(e);
        den += ex;
        acc0.x = fmaf(ex, v0.x, acc0.x); acc0.y = fmaf(ex, v0.y, acc0.y);
        acc0.z = fmaf(ex, v0.z, acc0.z); acc0.w = fmaf(ex, v0.w, acc0.w);
        acc1.x = fmaf(ex, v1.x, acc1.x); acc1.y = fmaf(ex, v1.y, acc1.y);
        acc1.z = fmaf(ex, v1.z, acc1.z); acc1.w = fmaf(ex, v1.w, acc1.w);
    }
    float inv = 1.0f / den;
    acc0.x *= inv; acc0.y *= inv; acc0.z *= inv; acc0.w *= inv;
    acc1.x *= inv; acc1.y *= inv; acc1.z *= inv; acc1.w *= inv;
    *(float4*)o       = acc0;
    *(float4*)(o + 4) = acc1;
}

/* ---------------- launch ---------------- */
extern "C" void kernel_launch(void* const* d_in, const int* in_sizes, int n_in,
                              void* d_out, int out_size) {
    const float* x  = (const float*)d_in[0];
    const int*   ei = (const int*)d_in[1];
    const float* Ww = (const float*)d_in[2];
    const float* Wb = (const float*)d_in[3];
    const float* a  = (const float*)d_in[4];
    float* out = (float*)d_out;

    detect_kernel<<<1, 256>>>(ei);
    init_kernel<<<(N_NODES * HEADS + 255) / 256, 256>>>();

    dim3 ggrid(F_OUT / 64, (N_NODES + 127) / 128);
    gemm_kernel<<<ggrid, 256>>>(x, Ww, Wb, a);

    deg_kernel<<<(N_EDGES + 255) / 256, 256>>>(ei);
    scan_kernel<<<1, 1024>>>();
    scatter_kernel<<<(N_EDGES + 255) / 256, 256>>>();

    agg_kernel<<<(N_NODES * 32 + 255) / 256, 256>>>(out);
}

// round 4
// speedup vs baseline: 3.1351x; 1.2214x over previous
#include <cuda_runtime.h>
#include <cuda_bf16.h>
#include <math.h>

#define N_NODES 50000
#define IN_DIM  256
#define OUT_DIM 128
#define HEADS   2
#define F_OUT   256
#define N_EDGES 800000

/* ---------------- scratch ---------------- */
__device__ float g_Wh[(size_t)N_NODES * F_OUT];
__device__ float g_s[N_NODES * HEADS];
__device__ float g_t[N_NODES * HEADS];
__device__ int   g_deg[N_NODES];
__device__ int   g_row[N_NODES + 1];
__device__ int   g_cursor[N_NODES];
__device__ int   g_csr_dst[N_EDGES];
__device__ int   g_esrc[N_EDGES];
__device__ int   g_edst[N_EDGES];
__device__ int   g_is64;

/* ---------------- 0: detect int32 vs int64 ---------------- */
__global__ void detect_kernel(const int* ei) {
    int v = ei[2 * threadIdx.x + 1];
    int any = __syncthreads_or(v != 0);
    if (threadIdx.x == 0) g_is64 = !any;
}

/* ---------------- 1: init ---------------- */
__global__ void init_kernel() {
    int i = blockIdx.x * blockDim.x + threadIdx.x;
    if (i < N_NODES) g_deg[i] = 0;
    if (i < N_NODES * HEADS) { g_s[i] = 0.0f; g_t[i] = 0.0f; }
}

/* ---------------- 2: 3xBF16 split-GEMM Wh = x@W + b, fused s/t -------- */
__device__ __forceinline__ void mma_bf16(float c[4], unsigned a0, unsigned a1,
                                         unsigned a2, unsigned a3,
                                         unsigned b0, unsigned b1) {
    asm volatile(
        "mma.sync.aligned.m16n8k16.row.col.f32.bf16.bf16.f32 "
        "{%0,%1,%2,%3},{%4,%5,%6,%7},{%8,%9},{%0,%1,%2,%3};"
        : "+f"(c[0]), "+f"(c[1]), "+f"(c[2]), "+f"(c[3])
        : "r"(a0), "r"(a1), "r"(a2), "r"(a3), "r"(b0), "r"(b1));
}

__device__ __forceinline__ void split2(float x, float y, unsigned& hi, unsigned& lo) {
    __nv_bfloat162 h = __floats2bfloat162_rn(x, y);
    float rx = x - __bfloat162float(h.x);
    float ry = y - __bfloat162float(h.y);
    __nv_bfloat162 l = __floats2bfloat162_rn(rx, ry);
    hi = *(unsigned*)&h;
    lo = *(unsigned*)&l;
}

__global__ void __launch_bounds__(256) gemm_kernel(const float* __restrict__ A,
                                                   const float* __restrict__ W,
                                                   const float* __restrict__ bias,
                                                   const float* __restrict__ a_vec) {
    /* pair-packed bf16x2 tiles: index [kp][row/n], k = 2*kp, 2*kp+1 */
    __shared__ unsigned Ah[16][136];
    __shared__ unsigned Al[16][136];
    __shared__ unsigned Bh[16][72];
    __shared__ unsigned Bl[16][72];

    const int bm = blockIdx.y * 128;
    const int bn = blockIdx.x * 64;
    const int tid  = threadIdx.x;
    const int lane = tid & 31;
    const int wid  = tid >> 5;
    const int warp_m = wid >> 1;
    const int warp_n = wid & 1;
    const int g  = lane >> 2;
    const int tc = lane & 3;
    const int head = (bn >= 128) ? 1 : 0;

    float c[2][4][4];
    #pragma unroll
    for (int mi = 0; mi < 2; mi++)
        #pragma unroll
        for (int ni = 0; ni < 4; ni++)
            #pragma unroll
            for (int r = 0; r < 4; r++) c[mi][ni][r] = 0.0f;

    for (int k0 = 0; k0 < IN_DIM; k0 += 32) {
        /* --- A tile 128 rows x 32 k --- */
        #pragma unroll
        for (int p = 0; p < 4; p++) {
            int row = p * 32 + (tid >> 3);
            int kq  = (tid & 7) * 4;          /* 4 consecutive k = 2 pairs */
            int kp  = kq >> 1;
            int gr  = bm + row;
            float4 v = make_float4(0.f, 0.f, 0.f, 0.f);
            if (gr < N_NODES)
                v = *(const float4*)&A[(size_t)gr * IN_DIM + k0 + kq];
            unsigned h0, l0, h1, l1;
            split2(v.x, v.y, h0, l0);
            split2(v.z, v.w, h1, l1);
            Ah[kp][row]     = h0;  Al[kp][row]     = l0;
            Ah[kp + 1][row] = h1;  Al[kp + 1][row] = l1;
        }
        /* --- B tile 32 k x 64 n --- */
        {
            int kp = tid >> 4;                /* 0..15 */
            int n4 = (tid & 15) * 4;
            const float* w0 = &W[(size_t)(k0 + 2 * kp) * F_OUT + bn + n4];
            float4 v0 = *(const float4*)w0;
            float4 v1 = *(const float4*)(w0 + F_OUT);
            unsigned h, l;
            split2(v0.x, v1.x, h, l); Bh[kp][n4 + 0] = h; Bl[kp][n4 + 0] = l;
            split2(v0.y, v1.y, h, l); Bh[kp][n4 + 1] = h; Bl[kp][n4 + 1] = l;
            split2(v0.z, v1.z, h, l); Bh[kp][n4 + 2] = h; Bl[kp][n4 + 2] = l;
            split2(v0.w, v1.w, h, l); Bh[kp][n4 + 3] = h; Bl[kp][n4 + 3] = l;
        }
        __syncthreads();

        #pragma unroll
        for (int kk = 0; kk < 2; kk++) {      /* two k16 slices per 32-chunk */
            unsigned ah[2][4], al[2][4], bh[4][2], bl[4][2];
            #pragma unroll
            for (int mi = 0; mi < 2; mi++) {
                int rb = warp_m * 32 + mi * 16;
                int kp = kk * 8 + tc;
                ah[mi][0] = Ah[kp][rb + g];      al[mi][0] = Al[kp][rb + g];
                ah[mi][1] = Ah[kp][rb + g + 8];  al[mi][1] = Al[kp][rb + g + 8];
                ah[mi][2] = Ah[kp + 4][rb + g];  al[mi][2] = Al[kp + 4][rb + g];
                ah[mi][3] = Ah[kp + 4][rb + g + 8]; al[mi][3] = Al[kp + 4][rb + g + 8];
            }
            #pragma unroll
            for (int ni = 0; ni < 4; ni++) {
                int n = warp_n * 32 + ni * 8 + g;
                int kp = kk * 8 + tc;
                bh[ni][0] = Bh[kp][n];     bl[ni][0] = Bl[kp][n];
                bh[ni][1] = Bh[kp + 4][n]; bl[ni][1] = Bl[kp + 4][n];
            }
            #pragma unroll
            for (int mi = 0; mi < 2; mi++)
                #pragma unroll
                for (int ni = 0; ni < 4; ni++) {
                    mma_bf16(c[mi][ni], ah[mi][0], ah[mi][1], ah[mi][2], ah[mi][3],
                             bl[ni][0], bl[ni][1]);
                    mma_bf16(c[mi][ni], al[mi][0], al[mi][1], al[mi][2], al[mi][3],
                             bh[ni][0], bh[ni][1]);
                    mma_bf16(c[mi][ni], ah[mi][0], ah[mi][1], ah[mi][2], ah[mi][3],
                             bh[ni][0], bh[ni][1]);
                }
        }
        __syncthreads();
    }

    /* epilogue: store Wh + partial s,t dots */
    #pragma unroll
    for (int mi = 0; mi < 2; mi++) {
        int r0 = bm + warp_m * 32 + mi * 16 + g;
        int r1 = r0 + 8;
        float ps0 = 0.f, pt0 = 0.f, ps1 = 0.f, pt1 = 0.f;
        #pragma unroll
        for (int ni = 0; ni < 4; ni++) {
            int cb = bn + warp_n * 32 + ni * 8 + tc * 2;
            int dloc = cb - head * OUT_DIM;
            float b0 = bias[cb], b1 = bias[cb + 1];
            float as0 = a_vec[dloc],           as1 = a_vec[dloc + 1];
            float ad0 = a_vec[OUT_DIM + dloc], ad1 = a_vec[OUT_DIM + dloc + 1];
            float v00 = c[mi][ni][0] + b0, v01 = c[mi][ni][1] + b1;
            float v10 = c[mi][ni][2] + b0, v11 = c[mi][ni][3] + b1;
            if (r0 < N_NODES) {
                g_Wh[(size_t)r0 * F_OUT + cb]     = v00;
                g_Wh[(size_t)r0 * F_OUT + cb + 1] = v01;
            }
            if (r1 < N_NODES) {
                g_Wh[(size_t)r1 * F_OUT + cb]     = v10;
                g_Wh[(size_t)r1 * F_OUT + cb + 1] = v11;
            }
            ps0 = fmaf(v00, as0, fmaf(v01, as1, ps0));
            pt0 = fmaf(v00, ad0, fmaf(v01, ad1, pt0));
            ps1 = fmaf(v10, as0, fmaf(v11, as1, ps1));
            pt1 = fmaf(v10, ad0, fmaf(v11, ad1, pt1));
        }
        #pragma unroll
        for (int o = 2; o > 0; o >>= 1) {
            ps0 += __shfl_down_sync(0xffffffffu, ps0, o);
            pt0 += __shfl_down_sync(0xffffffffu, pt0, o);
            ps1 += __shfl_down_sync(0xffffffffu, ps1, o);
            pt1 += __shfl_down_sync(0xffffffffu, pt1, o);
        }
        if (tc == 0) {
            if (r0 < N_NODES) {
                atomicAdd(&g_s[2 * r0 + head], ps0);
                atomicAdd(&g_t[2 * r0 + head], pt0);
            }
            if (r1 < N_NODES) {
                atomicAdd(&g_s[2 * r1 + head], ps1);
                atomicAdd(&g_t[2 * r1 + head], pt1);
            }
        }
    }
}

/* ---------------- 3: degree histogram + edge decode ---------------- */
__global__ void deg_kernel(const int* __restrict__ ei) {
    int i = blockIdx.x * blockDim.x + threadIdx.x;
    if (i >= N_EDGES) return;
    int src, dst;
    if (g_is64) { src = ei[2 * i]; dst = ei[2 * (N_EDGES + i)]; }
    else        { src = ei[i];     dst = ei[N_EDGES + i]; }
    g_esrc[i] = src;
    g_edst[i] = dst;
    atomicAdd(&g_deg[src], 1);
}

/* ---------------- 4: single-block exclusive scan (8 items/thread) ---- */
__global__ void scan_kernel() {
    const int tid = threadIdx.x, lane = tid & 31, wid = tid >> 5;
    __shared__ int wsum[32];
    __shared__ int s_carry;
    if (tid == 0) s_carry = 0;
    __syncthreads();
    for (int base = 0; base < N_NODES; base += 8192) {
        int i0 = base + tid * 8;
        int v[8], pref[8];
        int run = 0;
        #pragma unroll
        for (int j = 0; j < 8; j++) {
            v[j] = (i0 + j < N_NODES) ? g_deg[i0 + j] : 0;
            pref[j] = run;
            run += v[j];
        }
        int x = run;
        #pragma unroll
        for (int o = 1; o < 32; o <<= 1) {
            int y = __shfl_up_sync(0xffffffffu, x, o);
            if (lane >= o) x += y;
        }
        if (lane == 31) wsum[wid] = x;
        __syncthreads();
        if (wid == 0) {
            int w = wsum[lane];
            #pragma unroll
            for (int o = 1; o < 32; o <<= 1) {
                int y = __shfl_up_sync(0xffffffffu, w, o);
                if (lane >= o) w += y;
            }
            wsum[lane] = w;
        }
        __syncthreads();
        int off = s_carry + ((wid == 0) ? 0 : wsum[wid - 1]) + (x - run);
        #pragma unroll
        for (int j = 0; j < 8; j++) {
            int i = i0 + j;
            if (i < N_NODES) { g_row[i] = off + pref[j]; g_cursor[i] = off + pref[j]; }
        }
        __syncthreads();
        if (tid == 0) s_carry += wsum[31];
        __syncthreads();
    }
    if (tid == 0) g_row[N_NODES] = s_carry;
}

/* ---------------- 5: scatter into CSR ---------------- */
__global__ void scatter_kernel() {
    int i = blockIdx.x * blockDim.x + threadIdx.x;
    if (i >= N_EDGES) return;
    int src = g_esrc[i];
    int p = atomicAdd(&g_cursor[src], 1);
    g_csr_dst[p] = g_edst[i];
}

/* ---------------- 6: fused softmax+agg (warp per node) ---------------- */
__global__ void __launch_bounds__(256) agg_kernel(float* __restrict__ out) {
    int n = (blockIdx.x * blockDim.x + threadIdx.x) >> 5;
    int lane = threadIdx.x & 31;
    if (n >= N_NODES) return;
    int start = g_row[n], end = g_row[n + 1];
    float* o = out + (size_t)n * F_OUT + lane * 8;
    const float* whn = g_Wh + (size_t)n * F_OUT + lane * 8;

    if (start == end) {
        *(float4*)o       = *(const float4*)whn;
        *(float4*)(o + 4) = *(const float4*)(whn + 4);
        return;
    }

    int head = lane >> 4;
    float s_h = g_s[2 * n + head];
    float4 acc0 = make_float4(0.f, 0.f, 0.f, 0.f);
    float4 acc1 = make_float4(0.f, 0.f, 0.f, 0.f);
    float den = 0.0f;

    int i = start;
    for (; i + 1 < end; i += 2) {
        int d0 = g_csr_dst[i];
        int d1 = g_csr_dst[i + 1];
        float t0 = g_t[2 * d0 + head];
        float t1 = g_t[2 * d1 + head];
        const float4* w0 = (const float4*)(g_Wh + (size_t)d0 * F_OUT + lane * 8);
        const float4* w1 = (const float4*)(g_Wh + (size_t)d1 * F_OUT + lane * 8);
        float4 v00 = w0[0], v01 = w0[1];
        float4 v10 = w1[0], v11 = w1[1];
        float e0 = s_h + t0; e0 = e0 > 0.f ? e0 : 0.2f * e0;
        float e1 = s_h + t1; e1 = e1 > 0.f ? e1 : 0.2f * e1;
        float ex0 = expf(e0);
        float ex1 = expf(e1);
        den += ex0 + ex1;
        acc0.x = fmaf(ex0, v00.x, acc0.x); acc0.y = fmaf(ex0, v00.y, acc0.y);
        acc0.z = fmaf(ex0, v00.z, acc0.z); acc0.w = fmaf(ex0, v00.w, acc0.w);
        acc1.x = fmaf(ex0, v01.x, acc1.x); acc1.y = fmaf(ex0, v01.y, acc1.y);
        acc1.z = fmaf(ex0, v01.z, acc1.z); acc1.w = fmaf(ex0, v01.w, acc1.w);
        acc0.x = fmaf(ex1, v10.x, acc0.x); acc0.y = fmaf(ex1, v10.y, acc0.y);
        acc0.z = fmaf(ex1, v10.z, acc0.z); acc0.w = fmaf(ex1, v10.w, acc0.w);
        acc1.x = fmaf(ex1, v11.x, acc1.x); acc1.y = fmaf(ex1, v11.y, acc1.y);
        acc1.z = fmaf(ex1, v11.z, acc1.z); acc1.w = fmaf(ex1, v11.w, acc1.w);
    }
    if (i < end) {
        int d = g_csr_dst[i];
        float t = g_t[2 * d + head];
        const float4* w = (const float4*)(g_Wh + (size_t)d * F_OUT + lane * 8);
        float4 v0 = w[0], v1 = w[1];
        float e = s_h + t; e = e > 0.f ? e : 0.2f * e;
        float ex = expf(e);
        den += ex;
        acc0.x = fmaf(ex, v0.x, acc0.x); acc0.y = fmaf(ex, v0.y, acc0.y);
        acc0.z = fmaf(ex, v0.z, acc0.z); acc0.w = fmaf(ex, v0.w, acc0.w);
        acc1.x = fmaf(ex, v1.x, acc1.x); acc1.y = fmaf(ex, v1.y, acc1.y);
        acc1.z = fmaf(ex, v1.z, acc1.z); acc1.w = fmaf(ex, v1.w, acc1.w);
    }
    float inv = 1.0f / den;
    acc0.x *= inv; acc0.y *= inv; acc0.z *= inv; acc0.w *= inv;
    acc1.x *= inv; acc1.y *= inv; acc1.z *= inv; acc1.w *= inv;
    *(float4*)o       = acc0;
    *(float4*)(o + 4) = acc1;
}

/* ---------------- launch ---------------- */
extern "C" void kernel_launch(void* const* d_in, const int* in_sizes, int n_in,
                              void* d_out, int out_size) {
    const float* x  = (const float*)d_in[0];
    const int*   ei = (const int*)d_in[1];
    const float* Ww = (const float*)d_in[2];
    const float* Wb = (const float*)d_in[3];
    const float* a  = (const float*)d_in[4];
    float* out = (float*)d_out;

    detect_kernel<<<1, 256>>>(ei);
    init_kernel<<<(N_NODES * HEADS + 255) / 256, 256>>>();

    dim3 ggrid(F_OUT / 64, (N_NODES + 127) / 128);
    gemm_kernel<<<ggrid, 256>>>(x, Ww, Wb, a);

    deg_kernel<<<(N_EDGES + 255) / 256, 256>>>(ei);
    scan_kernel<<<1, 1024>>>();
    scatter_kernel<<<(N_EDGES + 255) / 256, 256>>>();

    agg_kernel<<<(N_NODES * 32 + 255) / 256, 256>>>(out);
}